// round 12
// baseline (speedup 1.0000x reference)
#include <cuda_runtime.h>

// ---------------------------------------------------------------------------
// Problem constants
// ---------------------------------------------------------------------------
#define BB   16
#define FC   96
#define HH   128
#define WW   128
#define HWSZ (HH*WW)          // 16384

// Scratch layout (float offsets into g_scratch)
static constexpr long long OF_FLOW  = 0;                       // 16*2*128*128
static constexpr long long OF_FEAT2 = OF_FLOW  + 16LL*2*HWSZ;  // 16*96*128*128
static constexpr long long OF_CORR  = OF_FEAT2 + 16LL*96*HWSZ; // 16*49*128*128
static constexpr long long OF_X1    = OF_CORR  + 16LL*49*HWSZ; // 16*128*HW
static constexpr long long OF_X2    = OF_X1    + 16LL*128*HWSZ;// 16*64*HW
static constexpr long long OF_X3    = OF_X2    + 16LL*64*HWSZ; // 16*32*HW
static constexpr long long OF_W1D   = OF_X3    + 16LL*32*HWSZ; // 49*9*128 float2
static constexpr long long OF_W2D   = OF_W1D   + 2LL*49*9*128; // 128*9*64 float2
static constexpr long long OF_W3D   = OF_W2D   + 2LL*128*9*64; // 64*9*32 float2
static constexpr long long OF_W4P   = OF_W3D   + 2LL*64*9*32;  // 32*25 float2
static constexpr long long SCRATCH_FLOATS = OF_W4P + 2LL*32*25;

__device__ __align__(16) float g_scratch[SCRATCH_FLOATS];

// ---------------------------------------------------------------------------
// Packed fp32x2 FMA (Blackwell FFMA2, 2x fp32 throughput)
// ---------------------------------------------------------------------------
__device__ __forceinline__ float2 ffma2(float2 a, float2 b, float2 c) {
    float2 d;
    asm("fma.rn.f32x2 %0, %1, %2, %3;"
        : "=l"(reinterpret_cast<unsigned long long&>(d))
        : "l"(reinterpret_cast<unsigned long long&>(a)),
          "l"(reinterpret_cast<unsigned long long&>(b)),
          "l"(reinterpret_cast<unsigned long long&>(c)));
    return d;
}

__device__ __forceinline__ float lrelu(float v) { return v >= 0.f ? v : 0.1f * v; }

// ---------------------------------------------------------------------------
// Fused weight prep (single launch so ncu capture lands on a hot kernel).
// w[co][ci][k] -> wD[(ci*9+k)*COUT + co] = (w, w)
// w4 (2,32,5,5) -> o[ci*25+t] = (w4[0,ci,t], w4[1,ci,t])
// ---------------------------------------------------------------------------
__device__ __forceinline__ void dup_one(const float* __restrict__ w, long long out_off,
                                        int COUT, int CINK, int t) {
    float2* o = reinterpret_cast<float2*>(g_scratch + out_off);
    int co = t / CINK;
    int r  = t - co * CINK;
    float v = w[t];
    o[(long long)r * COUT + co] = make_float2(v, v);
}

__global__ void prep_all_k(const float* __restrict__ w1, const float* __restrict__ w2,
                           const float* __restrict__ w3, const float* __restrict__ w4) {
    int t = blockIdx.x * 256 + threadIdx.x;
    const int N1 = 128 * 441, N2 = 64 * 1152, N3 = 32 * 576, N4 = 32 * 25;
    if (t < N1) { dup_one(w1, OF_W1D, 128, 441, t); return; }
    t -= N1;
    if (t < N2) { dup_one(w2, OF_W2D, 64, 1152, t); return; }
    t -= N2;
    if (t < N3) { dup_one(w3, OF_W3D, 32, 576, t); return; }
    t -= N3;
    if (t < N4) {
        float2* o = reinterpret_cast<float2*>(g_scratch + OF_W4P);
        o[t] = make_float2(w4[t], w4[800 + t]);
    }
}

// ---------------------------------------------------------------------------
// upflow: transposed conv, lhs_dilation=2, pad=2, groups=2, kernel=flip(wu)
// ---------------------------------------------------------------------------
__global__ void upflow_k(const float* __restrict__ tf, const float* __restrict__ wu) {
    int idx = blockIdx.x * 256 + threadIdx.x;
    if (idx >= BB * 2 * HWSZ) return;
    int ox = idx & 127, oy = (idx >> 7) & 127, c = (idx >> 14) & 1, b = idx >> 15;
    float acc = 0.f;
#pragma unroll
    for (int ky = 0; ky < 4; ky++) {
        int dy = oy + ky - 2;
        if ((dy & 1) || dy < 0 || dy > 126) continue;
        int iy = dy >> 1;
#pragma unroll
        for (int kx = 0; kx < 4; kx++) {
            int dx = ox + kx - 2;
            if ((dx & 1) || dx < 0 || dx > 126) continue;
            int ix = dx >> 1;
            acc += __ldg(&wu[c * 16 + (3 - ky) * 4 + (3 - kx)]) *
                   __ldg(&tf[((b * 2 + c) * 64 + iy) * 64 + ix]);
        }
    }
    g_scratch[OF_FLOW + idx] = acc;
}

// ---------------------------------------------------------------------------
// backward warp with zero-padding bilinear + validity mask
// ---------------------------------------------------------------------------
__global__ __launch_bounds__(128) void warp_k(const float* __restrict__ feat2in) {
    int idx = blockIdx.x * 128 + threadIdx.x;   // B*H*W threads
    int x = idx & 127, y = (idx >> 7) & 127, b = idx >> 14;
    const float* flow = g_scratch + OF_FLOW;
    float fx = (float)x + 2.5f * flow[((long long)(b * 2 + 0) * HH + y) * WW + x];
    float fy = (float)y + 2.5f * flow[((long long)(b * 2 + 1) * HH + y) * WW + x];
    float x0f = floorf(fx), y0f = floorf(fy);
    int x0 = (int)x0f, y0 = (int)y0f;
    float ax = fx - x0f, ay = fy - y0f;
    bool vx0 = (x0 >= 0) && (x0 <= 127);
    bool vx1 = (x0 + 1 >= 0) && (x0 + 1 <= 127);
    bool vy0 = (y0 >= 0) && (y0 <= 127);
    bool vy1 = (y0 + 1 >= 0) && (y0 + 1 <= 127);
    int xc0 = min(max(x0, 0), 127),     xc1 = min(max(x0 + 1, 0), 127);
    int yc0 = min(max(y0, 0), 127),     yc1 = min(max(y0 + 1, 0), 127);
    float wa = (1.f - ax) * (1.f - ay) * (float)(vx0 && vy0);
    float wb = ax * (1.f - ay)         * (float)(vx1 && vy0);
    float wc = (1.f - ax) * ay         * (float)(vx0 && vy1);
    float wd = ax * ay                 * (float)(vx1 && vy1);
    float ones = wa + wb + wc + wd;
    float m = ones > 0.999f ? 1.f : 0.f;
    wa *= m; wb *= m; wc *= m; wd *= m;
    const float* base = feat2in + (long long)b * FC * HWSZ;
    int o00 = yc0 * WW + xc0, o01 = yc0 * WW + xc1;
    int o10 = yc1 * WW + xc0, o11 = yc1 * WW + xc1;
    float* ob = g_scratch + OF_FEAT2 + (long long)b * FC * HWSZ + y * WW + x;
#pragma unroll 4
    for (int c = 0; c < FC; c++) {
        const float* p = base + (long long)c * HWSZ;
        ob[(long long)c * HWSZ] = wa * __ldg(p + o00) + wb * __ldg(p + o01) +
                                  wc * __ldg(p + o10) + wd * __ldg(p + o11);
    }
}

// ---------------------------------------------------------------------------
// correlation (MD=3 -> 49 displacements, mean over 96 ch) + lrelu — v3.
// (L1-bound at ~its structural floor; unchanged this round)
// ---------------------------------------------------------------------------
__global__ __launch_bounds__(256) void corr_k(const float* __restrict__ f1) {
    __shared__ float2 s2[4][8][136];          // 34816 B
    int tid = threadIdx.x;
    int x = tid & 127, ly = tid >> 7;          // ly 0..1
    int y0 = blockIdx.x * 2, b = blockIdx.y;
    int y = y0 + ly;

    float2 acc2[7][3];
    float  acc1[7];
#pragma unroll
    for (int dy = 0; dy < 7; dy++) {
#pragma unroll
        for (int e = 0; e < 3; e++) acc2[dy][e] = make_float2(0.f, 0.f);
        acc1[dy] = 0.f;
    }

    const float* f1b = f1 + (long long)b * FC * HWSZ;
    const float* f2b = g_scratch + OF_FEAT2 + (long long)b * FC * HWSZ;

    int rid = tid >> 3, sub = tid & 7;
    int st_cl = rid >> 3, st_r = rid & 7;
    int st_gy = y0 - 3 + st_r;
    bool rowok = (st_gy >= 0) && (st_gy < HH);
    const float* st_src = f2b + (long long)st_gy * WW;

    for (int c0 = 0; c0 < FC; c0 += 4) {
        {
            const float* src = st_src + (long long)(c0 + st_cl) * HWSZ;
            float2* row = s2[st_cl][st_r];
#pragma unroll
            for (int j = sub; j < 134; j += 8) {
                int gx = j - 3;
                float v = 0.f;
                if (rowok && gx >= 0 && gx < WW) v = __ldg(src + gx);
                row[j].x = v;
                if (j >= 1) row[j - 1].y = v;
            }
        }
        __syncthreads();
        float v1c[4];
#pragma unroll
        for (int cl = 0; cl < 4; cl++)
            v1c[cl] = __ldg(&f1b[(long long)(c0 + cl) * HWSZ + y * WW + x]);
#pragma unroll
        for (int cl = 0; cl < 4; cl++) {
            float  v1 = v1c[cl];
            float2 vv = make_float2(v1, v1);
#pragma unroll
            for (int dy = 0; dy < 7; dy++) {
                const float2* row = s2[cl][ly + dy];
                acc2[dy][0] = ffma2(row[x],     vv, acc2[dy][0]);
                acc2[dy][1] = ffma2(row[x + 2], vv, acc2[dy][1]);
                acc2[dy][2] = ffma2(row[x + 4], vv, acc2[dy][2]);
                acc1[dy] = fmaf(v1, row[x + 6].x, acc1[dy]);
            }
        }
        __syncthreads();
    }

    float* ob = g_scratch + OF_CORR + ((long long)b * 49 * HH + y) * WW + x;
#pragma unroll
    for (int dy = 0; dy < 7; dy++) {
#pragma unroll
        for (int e = 0; e < 3; e++) {
            ob[(long long)(dy * 7 + 2 * e)     * HWSZ] = lrelu(acc2[dy][e].x * (1.f / 96.f));
            ob[(long long)(dy * 7 + 2 * e + 1) * HWSZ] = lrelu(acc2[dy][e].y * (1.f / 96.f));
        }
        ob[(long long)(dy * 7 + 6) * HWSZ] = lrelu(acc1[dy] * (1.f / 96.f));
    }
}

// ---------------------------------------------------------------------------
// 3x3 conv + lrelu, f32x2 packed — v3 (issue-count optimized).
// Block (16,8,2) = 256 thr, output tile = 2 rows x 128 px x (8*COT) co.
// Thread = COT co x 8 px. Changes vs v2:
//   - COT=8 for conv1/conv2 (input LDS amortized over 2x channels)
//   - weight loads via LDS.128: two co's duplicated pairs per load
//   - __launch_bounds__(256,2) to guarantee 2 blocks/SM
// Issue mix per 288 FFMA2: 27 input LDS.64 + 36 weight LDS.128 (was ~454
// issues for the same math in v2 -> ~366 now).
// ---------------------------------------------------------------------------
template <int CIN, int COUT, int CICH, int COT>
__global__ __launch_bounds__(256, 2) void conv3x3_k(long long in_off, long long w_off,
                                                    const float* __restrict__ bias,
                                                    long long out_off) {
    constexpr int CO_TILE = 8 * COT;
    extern __shared__ float2 dyn[];
    float2* sW  = dyn;                           // [CICH][9*CO_TILE]
    float2* sIn = dyn + CICH * 9 * CO_TILE;      // [CICH][4][136]

    const float*  in = g_scratch + in_off;
    const float2* wD = reinterpret_cast<const float2*>(g_scratch + w_off);
    float*       out = g_scratch + out_off;

    int tx = threadIdx.x;                    // 16 -> 8 px each
    int ty = threadIdx.y;                    // 8  -> COT co each
    int tz = threadIdx.z;                    // 2  -> output row
    int tid = tz * 128 + ty * 16 + tx;
    int y0  = blockIdx.x * 2;
    int y   = y0 + tz;
    int co0 = blockIdx.y * CO_TILE;
    int b   = blockIdx.z;

    const float* inB = in + (long long)b * CIN * HWSZ;

    float2 acc[COT][4];
#pragma unroll
    for (int c = 0; c < COT; c++)
#pragma unroll
        for (int pp = 0; pp < 4; pp++) acc[c][pp] = make_float2(0.f, 0.f);

    // input-staging role: CICH*4 row-units (ci_l*4 + rr), 8 threads each.
    int rid = tid >> 3, sub = tid & 7;
    int st_cil = rid >> 2, st_rr = rid & 3;
    int st_gy  = y0 - 1 + st_rr;
    bool stage_ok = (st_cil < CICH);
    bool rowok = stage_ok && (st_gy >= 0) && (st_gy < HH);

    for (int ci0 = 0; ci0 < CIN; ci0 += CICH) {
        // ---- stage weights for CICH channels ----
        for (int i = tid; i < CICH * 9 * CO_TILE; i += 256) {
            int ci_l = i / (9 * CO_TILE);
            int r    = i - ci_l * 9 * CO_TILE;       // tap*CO_TILE + col
            sW[i] = wD[(long long)((ci0 + ci_l) * 9 + (r / CO_TILE)) * COUT
                       + co0 + (r & (CO_TILE - 1))];
        }
        // ---- stage shingled input pairs, rows y0-1..y0+2 ----
        if (stage_ok) {
            const float* src = inB + (long long)(ci0 + st_cil) * HWSZ + (long long)st_gy * WW;
            float2* row = sIn + (st_cil * 4 + st_rr) * 136;
            for (int j = sub; j < 131; j += 8) {
                int gx = j - 1;
                float v = 0.f;
                if (rowok && gx >= 0 && gx < WW) v = __ldg(src + gx);
                if (j <= 129) row[(j & 7) * 17 + (j >> 3)].x = v;
                if (j >= 1) { int u = j - 1; row[(u & 7) * 17 + (u >> 3)].y = v; }
            }
        }
        __syncthreads();
        // ---- compute CICH channels ----
        for (int ci_l = 0; ci_l < CICH; ci_l++) {
            const float2* wRow = sW + ci_l * 9 * CO_TILE + ty * COT;
#pragma unroll
            for (int ky = 0; ky < 3; ky++) {
                const float2* iRow = sIn + (ci_l * 4 + tz + ky) * 136;
                float2 s[9];
#pragma unroll
                for (int q = 0; q < 9; q++) {
                    int u = 8 * tx + q;
                    s[q] = iRow[(u & 7) * 17 + (u >> 3)];
                }
#pragma unroll
                for (int kx = 0; kx < 3; kx++) {
                    // two co's (w,w) pairs per LDS.128
                    const float4* wp = reinterpret_cast<const float4*>(
                        wRow + (ky * 3 + kx) * CO_TILE);
#pragma unroll
                    for (int c2 = 0; c2 < COT / 2; c2++) {
                        float4 wq = wp[c2];
                        float2 wa = make_float2(wq.x, wq.y);
                        float2 wb = make_float2(wq.z, wq.w);
#pragma unroll
                        for (int pp = 0; pp < 4; pp++) {
                            acc[2 * c2][pp]     = ffma2(s[kx + 2 * pp], wa, acc[2 * c2][pp]);
                            acc[2 * c2 + 1][pp] = ffma2(s[kx + 2 * pp], wb, acc[2 * c2 + 1][pp]);
                        }
                    }
                }
            }
        }
        __syncthreads();
    }
    // epilogue: bias + lrelu + store (float2 per pixel pair)
#pragma unroll
    for (int c = 0; c < COT; c++) {
        int co = co0 + ty * COT + c;
        float bv = __ldg(&bias[co]);
        float* ob = out + (((long long)b * COUT + co) * HH + y) * WW + 8 * tx;
#pragma unroll
        for (int pp = 0; pp < 4; pp++) {
            float2 r = acc[c][pp];
            r.x = lrelu(r.x + bv);
            r.y = lrelu(r.y + bv);
            *reinterpret_cast<float2*>(ob + 2 * pp) = r;
        }
    }
}

// ---------------------------------------------------------------------------
// conv4: 5x5, 32 -> 2 (paired over co), + bias + flow add -> d_out
// ---------------------------------------------------------------------------
__global__ __launch_bounds__(128) void conv4_k(const float* __restrict__ b4,
                                               float* __restrict__ out) {
    __shared__ float s[5][136];
    __shared__ float2 sw[800];
    int x = threadIdx.x;
    int y = blockIdx.x, b = blockIdx.y;
    const float2* w4p = reinterpret_cast<const float2*>(g_scratch + OF_W4P);
    const float* inb  = g_scratch + OF_X3 + (long long)b * 32 * HWSZ;
    for (int i = x; i < 800; i += 128) sw[i] = __ldg(&w4p[i]);
    float2 acc = make_float2(0.f, 0.f);
    for (int ci = 0; ci < 32; ci++) {
        for (int i = x; i < 660; i += 128) {
            int r = i / 132, col = i - r * 132;
            int gy = y - 2 + r, gx = col - 2;
            float v = 0.f;
            if (gy >= 0 && gy < HH && gx >= 0 && gx < WW)
                v = __ldg(&inb[(long long)ci * HWSZ + gy * WW + gx]);
            s[r][col] = v;
        }
        __syncthreads();
#pragma unroll
        for (int ky = 0; ky < 5; ky++)
#pragma unroll
            for (int kx = 0; kx < 5; kx++) {
                float v = s[ky][x + kx];
                float2 vv = make_float2(v, v);
                acc = ffma2(vv, sw[ci * 25 + ky * 5 + kx], acc);
            }
        __syncthreads();
    }
    const float* flow = g_scratch + OF_FLOW;
    long long o0 = ((long long)(b * 2 + 0) * HH + y) * WW + x;
    long long o1 = ((long long)(b * 2 + 1) * HH + y) * WW + x;
    out[o0] = flow[o0] + acc.x + __ldg(&b4[0]);
    out[o1] = flow[o1] + acc.y + __ldg(&b4[1]);
}

// ---------------------------------------------------------------------------
// Launch
// ---------------------------------------------------------------------------
extern "C" void kernel_launch(void* const* d_in, const int* in_sizes, int n_in,
                              void* d_out, int out_size) {
    const float* feat1 = (const float*)d_in[2];
    const float* feat2 = (const float*)d_in[3];
    const float* tflow = (const float*)d_in[4];
    const float* wu    = (const float*)d_in[5];
    const float* w1    = (const float*)d_in[6];
    const float* b1    = (const float*)d_in[7];
    const float* w2    = (const float*)d_in[8];
    const float* b2    = (const float*)d_in[9];
    const float* w3    = (const float*)d_in[10];
    const float* b3    = (const float*)d_in[11];
    const float* w4    = (const float*)d_in[12];
    const float* b4    = (const float*)d_in[13];
    float* out = (float*)d_out;

    // dynamic smem: (CICH*9*CO_TILE + CICH*4*136) float2
    const int SM1 = (7 * 9 * 64 + 7 * 4 * 136) * 8;   // 62720 (COT=8, CICH=7)
    const int SM2 = (8 * 9 * 64 + 8 * 4 * 136) * 8;   // 71680 (COT=8, CICH=8)
    const int SM3 = (8 * 9 * 32 + 8 * 4 * 136) * 8;   // 53248 (COT=4, CICH=8)
    cudaFuncSetAttribute(conv3x3_k<49, 128, 7, 8>, cudaFuncAttributeMaxDynamicSharedMemorySize, SM1);
    cudaFuncSetAttribute(conv3x3_k<128, 64, 8, 8>, cudaFuncAttributeMaxDynamicSharedMemorySize, SM2);
    cudaFuncSetAttribute(conv3x3_k<64, 32, 8, 4>,  cudaFuncAttributeMaxDynamicSharedMemorySize, SM3);

    // 1 prep launch so ncu's skip-count lands on a hot kernel
    prep_all_k<<<(128*441 + 64*1152 + 32*576 + 800 + 255) / 256, 256>>>(w1, w2, w3, w4);

    upflow_k<<<2048, 256>>>(tflow, wu);
    warp_k<<<2048, 128>>>(feat2);
    corr_k<<<dim3(64, 16), 256>>>(feat1);
    conv3x3_k<49, 128, 7, 8><<<dim3(64, 2, 16), dim3(16, 8, 2), SM1>>>(OF_CORR, OF_W1D, b1, OF_X1);
    conv3x3_k<128, 64, 8, 8><<<dim3(64, 1, 16), dim3(16, 8, 2), SM2>>>(OF_X1, OF_W2D, b2, OF_X2);
    conv3x3_k<64, 32, 8, 4><<<dim3(64, 1, 16), dim3(16, 8, 2), SM3>>>(OF_X2, OF_W3D, b3, OF_X3);
    conv4_k<<<dim3(128, 16), 128>>>(b4, out);
}

// round 13
// speedup vs baseline: 1.0826x; 1.0826x over previous
#include <cuda_runtime.h>

// ---------------------------------------------------------------------------
// Problem constants
// ---------------------------------------------------------------------------
#define BB   16
#define FC   96
#define HH   128
#define WW   128
#define HWSZ (HH*WW)          // 16384

// Scratch layout (float offsets into g_scratch)
static constexpr long long OF_FLOW  = 0;                       // 16*2*128*128
static constexpr long long OF_FEAT2 = OF_FLOW  + 16LL*2*HWSZ;  // 16*96*128*128
static constexpr long long OF_CORR  = OF_FEAT2 + 16LL*96*HWSZ; // 16*49*128*128
static constexpr long long OF_X1    = OF_CORR  + 16LL*49*HWSZ; // 16*128*HW
static constexpr long long OF_X2    = OF_X1    + 16LL*128*HWSZ;// 16*64*HW
static constexpr long long OF_X3    = OF_X2    + 16LL*64*HWSZ; // 16*32*HW
static constexpr long long OF_W1D   = OF_X3    + 16LL*32*HWSZ; // 49*9*128 float2
static constexpr long long OF_W2D   = OF_W1D   + 2LL*49*9*128; // 128*9*64 float2
static constexpr long long OF_W3D   = OF_W2D   + 2LL*128*9*64; // 64*9*32 float2
static constexpr long long OF_W4P   = OF_W3D   + 2LL*64*9*32;  // 32*25 float2
static constexpr long long SCRATCH_FLOATS = OF_W4P + 2LL*32*25;

__device__ __align__(16) float g_scratch[SCRATCH_FLOATS];

// ---------------------------------------------------------------------------
// Packed fp32x2 FMA (Blackwell FFMA2, 2x fp32 throughput)
// ---------------------------------------------------------------------------
__device__ __forceinline__ float2 ffma2(float2 a, float2 b, float2 c) {
    float2 d;
    asm("fma.rn.f32x2 %0, %1, %2, %3;"
        : "=l"(reinterpret_cast<unsigned long long&>(d))
        : "l"(reinterpret_cast<unsigned long long&>(a)),
          "l"(reinterpret_cast<unsigned long long&>(b)),
          "l"(reinterpret_cast<unsigned long long&>(c)));
    return d;
}

__device__ __forceinline__ float lrelu(float v) { return v >= 0.f ? v : 0.1f * v; }

// ---------------------------------------------------------------------------
// Fused weight prep (single launch so ncu capture lands on a hot kernel).
// w[co][ci][k] -> wD[(ci*9+k)*COUT + co] = (w, w)
// w4 (2,32,5,5) -> o[ci*25+t] = (w4[0,ci,t], w4[1,ci,t])
// ---------------------------------------------------------------------------
__device__ __forceinline__ void dup_one(const float* __restrict__ w, long long out_off,
                                        int COUT, int CINK, int t) {
    float2* o = reinterpret_cast<float2*>(g_scratch + out_off);
    int co = t / CINK;
    int r  = t - co * CINK;
    float v = w[t];
    o[(long long)r * COUT + co] = make_float2(v, v);
}

__global__ void prep_all_k(const float* __restrict__ w1, const float* __restrict__ w2,
                           const float* __restrict__ w3, const float* __restrict__ w4) {
    int t = blockIdx.x * 256 + threadIdx.x;
    const int N1 = 128 * 441, N2 = 64 * 1152, N3 = 32 * 576, N4 = 32 * 25;
    if (t < N1) { dup_one(w1, OF_W1D, 128, 441, t); return; }
    t -= N1;
    if (t < N2) { dup_one(w2, OF_W2D, 64, 1152, t); return; }
    t -= N2;
    if (t < N3) { dup_one(w3, OF_W3D, 32, 576, t); return; }
    t -= N3;
    if (t < N4) {
        float2* o = reinterpret_cast<float2*>(g_scratch + OF_W4P);
        o[t] = make_float2(w4[t], w4[800 + t]);
    }
}

// ---------------------------------------------------------------------------
// upflow: transposed conv, lhs_dilation=2, pad=2, groups=2, kernel=flip(wu)
// ---------------------------------------------------------------------------
__global__ void upflow_k(const float* __restrict__ tf, const float* __restrict__ wu) {
    int idx = blockIdx.x * 256 + threadIdx.x;
    if (idx >= BB * 2 * HWSZ) return;
    int ox = idx & 127, oy = (idx >> 7) & 127, c = (idx >> 14) & 1, b = idx >> 15;
    float acc = 0.f;
#pragma unroll
    for (int ky = 0; ky < 4; ky++) {
        int dy = oy + ky - 2;
        if ((dy & 1) || dy < 0 || dy > 126) continue;
        int iy = dy >> 1;
#pragma unroll
        for (int kx = 0; kx < 4; kx++) {
            int dx = ox + kx - 2;
            if ((dx & 1) || dx < 0 || dx > 126) continue;
            int ix = dx >> 1;
            acc += __ldg(&wu[c * 16 + (3 - ky) * 4 + (3 - kx)]) *
                   __ldg(&tf[((b * 2 + c) * 64 + iy) * 64 + ix]);
        }
    }
    g_scratch[OF_FLOW + idx] = acc;
}

// ---------------------------------------------------------------------------
// backward warp with zero-padding bilinear + validity mask
// ---------------------------------------------------------------------------
__global__ __launch_bounds__(128) void warp_k(const float* __restrict__ feat2in) {
    int idx = blockIdx.x * 128 + threadIdx.x;   // B*H*W threads
    int x = idx & 127, y = (idx >> 7) & 127, b = idx >> 14;
    const float* flow = g_scratch + OF_FLOW;
    float fx = (float)x + 2.5f * flow[((long long)(b * 2 + 0) * HH + y) * WW + x];
    float fy = (float)y + 2.5f * flow[((long long)(b * 2 + 1) * HH + y) * WW + x];
    float x0f = floorf(fx), y0f = floorf(fy);
    int x0 = (int)x0f, y0 = (int)y0f;
    float ax = fx - x0f, ay = fy - y0f;
    bool vx0 = (x0 >= 0) && (x0 <= 127);
    bool vx1 = (x0 + 1 >= 0) && (x0 + 1 <= 127);
    bool vy0 = (y0 >= 0) && (y0 <= 127);
    bool vy1 = (y0 + 1 >= 0) && (y0 + 1 <= 127);
    int xc0 = min(max(x0, 0), 127),     xc1 = min(max(x0 + 1, 0), 127);
    int yc0 = min(max(y0, 0), 127),     yc1 = min(max(y0 + 1, 0), 127);
    float wa = (1.f - ax) * (1.f - ay) * (float)(vx0 && vy0);
    float wb = ax * (1.f - ay)         * (float)(vx1 && vy0);
    float wc = (1.f - ax) * ay         * (float)(vx0 && vy1);
    float wd = ax * ay                 * (float)(vx1 && vy1);
    float ones = wa + wb + wc + wd;
    float m = ones > 0.999f ? 1.f : 0.f;
    wa *= m; wb *= m; wc *= m; wd *= m;
    const float* base = feat2in + (long long)b * FC * HWSZ;
    int o00 = yc0 * WW + xc0, o01 = yc0 * WW + xc1;
    int o10 = yc1 * WW + xc0, o11 = yc1 * WW + xc1;
    float* ob = g_scratch + OF_FEAT2 + (long long)b * FC * HWSZ + y * WW + x;
#pragma unroll 4
    for (int c = 0; c < FC; c++) {
        const float* p = base + (long long)c * HWSZ;
        ob[(long long)c * HWSZ] = wa * __ldg(p + o00) + wb * __ldg(p + o01) +
                                  wc * __ldg(p + o10) + wd * __ldg(p + o11);
    }
}

// ---------------------------------------------------------------------------
// correlation (MD=3 -> 49 displacements, mean over 96 ch) + lrelu — v3.
// (L1-crossbar bound at ~its structural floor; unchanged)
// ---------------------------------------------------------------------------
__global__ __launch_bounds__(256) void corr_k(const float* __restrict__ f1) {
    __shared__ float2 s2[4][8][136];          // 34816 B
    int tid = threadIdx.x;
    int x = tid & 127, ly = tid >> 7;          // ly 0..1
    int y0 = blockIdx.x * 2, b = blockIdx.y;
    int y = y0 + ly;

    float2 acc2[7][3];
    float  acc1[7];
#pragma unroll
    for (int dy = 0; dy < 7; dy++) {
#pragma unroll
        for (int e = 0; e < 3; e++) acc2[dy][e] = make_float2(0.f, 0.f);
        acc1[dy] = 0.f;
    }

    const float* f1b = f1 + (long long)b * FC * HWSZ;
    const float* f2b = g_scratch + OF_FEAT2 + (long long)b * FC * HWSZ;

    int rid = tid >> 3, sub = tid & 7;
    int st_cl = rid >> 3, st_r = rid & 7;
    int st_gy = y0 - 3 + st_r;
    bool rowok = (st_gy >= 0) && (st_gy < HH);
    const float* st_src = f2b + (long long)st_gy * WW;

    for (int c0 = 0; c0 < FC; c0 += 4) {
        {
            const float* src = st_src + (long long)(c0 + st_cl) * HWSZ;
            float2* row = s2[st_cl][st_r];
#pragma unroll
            for (int j = sub; j < 134; j += 8) {
                int gx = j - 3;
                float v = 0.f;
                if (rowok && gx >= 0 && gx < WW) v = __ldg(src + gx);
                row[j].x = v;
                if (j >= 1) row[j - 1].y = v;
            }
        }
        __syncthreads();
        float v1c[4];
#pragma unroll
        for (int cl = 0; cl < 4; cl++)
            v1c[cl] = __ldg(&f1b[(long long)(c0 + cl) * HWSZ + y * WW + x]);
#pragma unroll
        for (int cl = 0; cl < 4; cl++) {
            float  v1 = v1c[cl];
            float2 vv = make_float2(v1, v1);
#pragma unroll
            for (int dy = 0; dy < 7; dy++) {
                const float2* row = s2[cl][ly + dy];
                acc2[dy][0] = ffma2(row[x],     vv, acc2[dy][0]);
                acc2[dy][1] = ffma2(row[x + 2], vv, acc2[dy][1]);
                acc2[dy][2] = ffma2(row[x + 4], vv, acc2[dy][2]);
                acc1[dy] = fmaf(v1, row[x + 6].x, acc1[dy]);
            }
        }
        __syncthreads();
    }

    float* ob = g_scratch + OF_CORR + ((long long)b * 49 * HH + y) * WW + x;
#pragma unroll
    for (int dy = 0; dy < 7; dy++) {
#pragma unroll
        for (int e = 0; e < 3; e++) {
            ob[(long long)(dy * 7 + 2 * e)     * HWSZ] = lrelu(acc2[dy][e].x * (1.f / 96.f));
            ob[(long long)(dy * 7 + 2 * e + 1) * HWSZ] = lrelu(acc2[dy][e].y * (1.f / 96.f));
        }
        ob[(long long)(dy * 7 + 6) * HWSZ] = lrelu(acc1[dy] * (1.f / 96.f));
    }
}

// ---------------------------------------------------------------------------
// 3x3 conv + lrelu, f32x2 packed — v4 = R11 tile (COT=4) + register-prefetch
// software pipeline for the input staging.
// Block (16,8,2) = 256 thr, output tile = 2 rows x 128 px x 32 co.
// Per chunk (CICH channels):
//   STS(prefetched input regs) + weight LDG->STS ; barrier ;
//   LDG(next chunk input) -> regs  [latency hides under compute] ;
//   compute ; barrier.
// ---------------------------------------------------------------------------
template <int CIN, int COUT, int CICH>
__global__ __launch_bounds__(256, 2) void conv3x3_k(long long in_off, long long w_off,
                                                    const float* __restrict__ bias,
                                                    long long out_off) {
    constexpr int CO_TILE = 32;
    constexpr int COT = 4;
    extern __shared__ float2 dyn[];
    float2* sW  = dyn;                       // [CICH][9*32]
    float2* sIn = dyn + CICH * 288;          // [CICH][4][136]

    const float*  in = g_scratch + in_off;
    const float2* wD = reinterpret_cast<const float2*>(g_scratch + w_off);
    float*       out = g_scratch + out_off;

    int tx = threadIdx.x;                    // 16 -> 8 px each
    int ty = threadIdx.y;                    // 8  -> 4 co each
    int tz = threadIdx.z;                    // 2  -> output row
    int tid = tz * 128 + ty * 16 + tx;
    int y0  = blockIdx.x * 2;
    int y   = y0 + tz;
    int co0 = blockIdx.y * CO_TILE;
    int b   = blockIdx.z;

    const float* inB = in + (long long)b * CIN * HWSZ;

    float2 acc[COT][4];
#pragma unroll
    for (int c = 0; c < COT; c++)
#pragma unroll
        for (int pp = 0; pp < 4; pp++) acc[c][pp] = make_float2(0.f, 0.f);

    // input-staging role: CICH*4 row-units (ci_l*4 + rr), 8 threads each.
    int rid = tid >> 3, sub = tid & 7;
    int st_cil = rid >> 2, st_rr = rid & 3;
    int st_gy  = y0 - 1 + st_rr;
    bool stage_ok = (st_cil < CICH);
    bool rowok = stage_ok && (st_gy >= 0) && (st_gy < HH);
    const float* st_base = inB + (long long)st_cil * HWSZ + (long long)st_gy * WW;

    // prefetch registers: j = sub + 8k, j < 131  (<=17 values)
    float pf[17];

    // ---- prologue: prefetch chunk 0 ----
    if (stage_ok) {
#pragma unroll
        for (int k = 0; k < 17; k++) {
            int j = sub + 8 * k;
            if (j < 131) {
                int gx = j - 1;
                float v = 0.f;
                if (rowok && gx >= 0 && gx < WW) v = __ldg(st_base + gx);
                pf[k] = v;
            }
        }
    }

    for (int ci0 = 0; ci0 < CIN; ci0 += CICH) {
        // ---- stage weights for CICH channels (synchronous, L2-hot) ----
        for (int i = tid; i < CICH * 288; i += 256) {
            int ci_l = i / 288;
            int r    = i - ci_l * 288;           // k*32 + col
            sW[i] = wD[(long long)((ci0 + ci_l) * 9 + (r >> 5)) * COUT + co0 + (r & 31)];
        }
        // ---- STS prefetched input (shingled pairs), rows y0-1..y0+2 ----
        if (stage_ok) {
            float2* row = sIn + (st_cil * 4 + st_rr) * 136;
#pragma unroll
            for (int k = 0; k < 17; k++) {
                int j = sub + 8 * k;
                if (j < 131) {
                    float v = pf[k];
                    if (j <= 129) row[(j & 7) * 17 + (j >> 3)].x = v;
                    if (j >= 1) { int u = j - 1; row[(u & 7) * 17 + (u >> 3)].y = v; }
                }
            }
        }
        __syncthreads();
        // ---- prefetch next chunk's input (latency hides under compute) ----
        if (stage_ok && ci0 + CICH < CIN) {
            const float* src = st_base + (long long)(ci0 + CICH) * HWSZ;
#pragma unroll
            for (int k = 0; k < 17; k++) {
                int j = sub + 8 * k;
                if (j < 131) {
                    int gx = j - 1;
                    float v = 0.f;
                    if (rowok && gx >= 0 && gx < WW) v = __ldg(src + gx);
                    pf[k] = v;
                }
            }
        }
        // ---- compute CICH channels ----
        for (int ci_l = 0; ci_l < CICH; ci_l++) {
            const float2* wRow = sW + ci_l * 288 + ty * COT;
#pragma unroll
            for (int ky = 0; ky < 3; ky++) {
                const float2* iRow = sIn + (ci_l * 4 + tz + ky) * 136;
                float2 s[9];
#pragma unroll
                for (int q = 0; q < 9; q++) {
                    int u = 8 * tx + q;
                    s[q] = iRow[(u & 7) * 17 + (u >> 3)];
                }
#pragma unroll
                for (int kx = 0; kx < 3; kx++) {
#pragma unroll
                    for (int c = 0; c < COT; c++) {
                        float2 wv = wRow[(ky * 3 + kx) * 32 + c];
#pragma unroll
                        for (int pp = 0; pp < 4; pp++)
                            acc[c][pp] = ffma2(s[kx + 2 * pp], wv, acc[c][pp]);
                    }
                }
            }
        }
        __syncthreads();
    }
    // epilogue: bias + lrelu + store (float2 per pixel pair)
#pragma unroll
    for (int c = 0; c < COT; c++) {
        int co = co0 + ty * COT + c;
        float bv = __ldg(&bias[co]);
        float* ob = out + (((long long)b * COUT + co) * HH + y) * WW + 8 * tx;
#pragma unroll
        for (int pp = 0; pp < 4; pp++) {
            float2 r = acc[c][pp];
            r.x = lrelu(r.x + bv);
            r.y = lrelu(r.y + bv);
            *reinterpret_cast<float2*>(ob + 2 * pp) = r;
        }
    }
}

// ---------------------------------------------------------------------------
// conv4: 5x5, 32 -> 2 (paired over co), + bias + flow add -> d_out
// ---------------------------------------------------------------------------
__global__ __launch_bounds__(128) void conv4_k(const float* __restrict__ b4,
                                               float* __restrict__ out) {
    __shared__ float s[5][136];
    __shared__ float2 sw[800];
    int x = threadIdx.x;
    int y = blockIdx.x, b = blockIdx.y;
    const float2* w4p = reinterpret_cast<const float2*>(g_scratch + OF_W4P);
    const float* inb  = g_scratch + OF_X3 + (long long)b * 32 * HWSZ;
    for (int i = x; i < 800; i += 128) sw[i] = __ldg(&w4p[i]);
    float2 acc = make_float2(0.f, 0.f);
    for (int ci = 0; ci < 32; ci++) {
        for (int i = x; i < 660; i += 128) {
            int r = i / 132, col = i - r * 132;
            int gy = y - 2 + r, gx = col - 2;
            float v = 0.f;
            if (gy >= 0 && gy < HH && gx >= 0 && gx < WW)
                v = __ldg(&inb[(long long)ci * HWSZ + gy * WW + gx]);
            s[r][col] = v;
        }
        __syncthreads();
#pragma unroll
        for (int ky = 0; ky < 5; ky++)
#pragma unroll
            for (int kx = 0; kx < 5; kx++) {
                float v = s[ky][x + kx];
                float2 vv = make_float2(v, v);
                acc = ffma2(vv, sw[ci * 25 + ky * 5 + kx], acc);
            }
        __syncthreads();
    }
    const float* flow = g_scratch + OF_FLOW;
    long long o0 = ((long long)(b * 2 + 0) * HH + y) * WW + x;
    long long o1 = ((long long)(b * 2 + 1) * HH + y) * WW + x;
    out[o0] = flow[o0] + acc.x + __ldg(&b4[0]);
    out[o1] = flow[o1] + acc.y + __ldg(&b4[1]);
}

// ---------------------------------------------------------------------------
// Launch
// ---------------------------------------------------------------------------
extern "C" void kernel_launch(void* const* d_in, const int* in_sizes, int n_in,
                              void* d_out, int out_size) {
    const float* feat1 = (const float*)d_in[2];
    const float* feat2 = (const float*)d_in[3];
    const float* tflow = (const float*)d_in[4];
    const float* wu    = (const float*)d_in[5];
    const float* w1    = (const float*)d_in[6];
    const float* b1    = (const float*)d_in[7];
    const float* w2    = (const float*)d_in[8];
    const float* b2    = (const float*)d_in[9];
    const float* w3    = (const float*)d_in[10];
    const float* b3    = (const float*)d_in[11];
    const float* w4    = (const float*)d_in[12];
    const float* b4    = (const float*)d_in[13];
    float* out = (float*)d_out;

    // dynamic smem sizes: (CICH*288 + CICH*4*136) * sizeof(float2)
    const int SM1 = (7 * 288 + 7 * 4 * 136) * 8;   // 46592
    const int SM2 = (8 * 288 + 8 * 4 * 136) * 8;   // 53248
    cudaFuncSetAttribute(conv3x3_k<49, 128, 7>, cudaFuncAttributeMaxDynamicSharedMemorySize, SM1);
    cudaFuncSetAttribute(conv3x3_k<128, 64, 8>, cudaFuncAttributeMaxDynamicSharedMemorySize, SM2);
    cudaFuncSetAttribute(conv3x3_k<64, 32, 8>,  cudaFuncAttributeMaxDynamicSharedMemorySize, SM2);

    // 1 prep launch so ncu's skip-count lands on a hot kernel
    prep_all_k<<<(128*441 + 64*1152 + 32*576 + 800 + 255) / 256, 256>>>(w1, w2, w3, w4);

    upflow_k<<<2048, 256>>>(tflow, wu);
    warp_k<<<2048, 128>>>(feat2);
    corr_k<<<dim3(64, 16), 256>>>(feat1);
    conv3x3_k<49, 128, 7><<<dim3(64, 4, 16), dim3(16, 8, 2), SM1>>>(OF_CORR, OF_W1D, b1, OF_X1);
    conv3x3_k<128, 64, 8><<<dim3(64, 2, 16), dim3(16, 8, 2), SM2>>>(OF_X1, OF_W2D, b2, OF_X2);
    conv3x3_k<64, 32, 8><<<dim3(64, 1, 16), dim3(16, 8, 2), SM2>>>(OF_X2, OF_W3D, b3, OF_X3);
    conv4_k<<<dim3(128, 16), 128>>>(b4, out);
}

// round 15
// speedup vs baseline: 1.1376x; 1.0508x over previous
#include <cuda_runtime.h>

// ---------------------------------------------------------------------------
// Problem constants
// ---------------------------------------------------------------------------
#define BB   16
#define FC   96
#define HH   128
#define WW   128
#define HWSZ (HH*WW)          // 16384

// Scratch layout (float offsets into g_scratch)
static constexpr long long OF_FLOW  = 0;                       // 16*2*128*128
static constexpr long long OF_FEAT2 = OF_FLOW  + 16LL*2*HWSZ;  // 16*96*128*128
static constexpr long long OF_CORR  = OF_FEAT2 + 16LL*96*HWSZ; // 16*49*128*128
static constexpr long long OF_X1    = OF_CORR  + 16LL*49*HWSZ; // 16*128*HW
static constexpr long long OF_X2    = OF_X1    + 16LL*128*HWSZ;// 16*64*HW
static constexpr long long OF_X3    = OF_X2    + 16LL*64*HWSZ; // 16*32*HW
static constexpr long long OF_W1D   = OF_X3    + 16LL*32*HWSZ; // 49*9*128 float2
static constexpr long long OF_W2D   = OF_W1D   + 2LL*49*9*128; // 128*9*64 float2
static constexpr long long OF_W3D   = OF_W2D   + 2LL*128*9*64; // 64*9*32 float2
static constexpr long long OF_W4P   = OF_W3D   + 2LL*64*9*32;  // 32*25 float2
static constexpr long long SCRATCH_FLOATS = OF_W4P + 2LL*32*25;

__device__ __align__(16) float g_scratch[SCRATCH_FLOATS];

// ---------------------------------------------------------------------------
// Packed fp32x2 FMA (Blackwell FFMA2) + cp.async helpers
// ---------------------------------------------------------------------------
__device__ __forceinline__ float2 ffma2(float2 a, float2 b, float2 c) {
    float2 d;
    asm("fma.rn.f32x2 %0, %1, %2, %3;"
        : "=l"(reinterpret_cast<unsigned long long&>(d))
        : "l"(reinterpret_cast<unsigned long long&>(a)),
          "l"(reinterpret_cast<unsigned long long&>(b)),
          "l"(reinterpret_cast<unsigned long long&>(c)));
    return d;
}

__device__ __forceinline__ void cp_async16(void* smem_dst, const void* gmem_src) {
    unsigned saddr = (unsigned)__cvta_generic_to_shared(smem_dst);
    asm volatile("cp.async.cg.shared.global [%0], [%1], 16;" :: "r"(saddr), "l"(gmem_src));
}
#define CP_COMMIT() asm volatile("cp.async.commit_group;")
#define CP_WAIT0()  asm volatile("cp.async.wait_group 0;")

__device__ __forceinline__ float lrelu(float v) { return v >= 0.f ? v : 0.1f * v; }

// ---------------------------------------------------------------------------
// Fused weight prep.
// w[co][ci][k] -> wD[(ci*9+k)*COUT + co] = (w, w)
// w4 (2,32,5,5) -> o[ci*25+t] = (w4[0,ci,t], w4[1,ci,t])
// ---------------------------------------------------------------------------
__device__ __forceinline__ void dup_one(const float* __restrict__ w, long long out_off,
                                        int COUT, int CINK, int t) {
    float2* o = reinterpret_cast<float2*>(g_scratch + out_off);
    int co = t / CINK;
    int r  = t - co * CINK;
    float v = w[t];
    o[(long long)r * COUT + co] = make_float2(v, v);
}

__global__ void prep_all_k(const float* __restrict__ w1, const float* __restrict__ w2,
                           const float* __restrict__ w3, const float* __restrict__ w4) {
    int t = blockIdx.x * 256 + threadIdx.x;
    const int N1 = 128 * 441, N2 = 64 * 1152, N3 = 32 * 576, N4 = 32 * 25;
    if (t < N1) { dup_one(w1, OF_W1D, 128, 441, t); return; }
    t -= N1;
    if (t < N2) { dup_one(w2, OF_W2D, 64, 1152, t); return; }
    t -= N2;
    if (t < N3) { dup_one(w3, OF_W3D, 32, 576, t); return; }
    t -= N3;
    if (t < N4) {
        float2* o = reinterpret_cast<float2*>(g_scratch + OF_W4P);
        o[t] = make_float2(w4[t], w4[800 + t]);
    }
}

// ---------------------------------------------------------------------------
// FUSED upflow + backward warp. Each thread computes its own 2-component
// upsampled flow inline (<=16 taps/channel, wu is L1-resident), writes it to
// OF_FLOW (needed by conv4 epilogue), then does the bilinear gather.
// Eliminates the separate upflow launch AND moves conv1 to the 4th launch so
// ncu's fixed capture index finally lands on a conv.
// ---------------------------------------------------------------------------
__global__ __launch_bounds__(128) void upwarp_k(const float* __restrict__ tf,
                                                const float* __restrict__ wu,
                                                const float* __restrict__ feat2in) {
    int idx = blockIdx.x * 128 + threadIdx.x;   // B*H*W threads
    int x = idx & 127, y = (idx >> 7) & 127, b = idx >> 14;

    // ---- inline upflow (transposed conv, lhs_dilation=2, pad=2, groups=2) ----
    float fl[2];
#pragma unroll
    for (int c = 0; c < 2; c++) {
        float a = 0.f;
#pragma unroll
        for (int ky = 0; ky < 4; ky++) {
            int dy = y + ky - 2;
            if ((dy & 1) || dy < 0 || dy > 126) continue;
            int iy = dy >> 1;
#pragma unroll
            for (int kx = 0; kx < 4; kx++) {
                int dx = x + kx - 2;
                if ((dx & 1) || dx < 0 || dx > 126) continue;
                int ix = dx >> 1;
                a += __ldg(&wu[c * 16 + (3 - ky) * 4 + (3 - kx)]) *
                     __ldg(&tf[((b * 2 + c) * 64 + iy) * 64 + ix]);
            }
        }
        fl[c] = a;
        g_scratch[OF_FLOW + ((long long)(b * 2 + c) * HH + y) * WW + x] = a;
    }

    // ---- backward warp with zero-pad bilinear + validity mask ----
    float fx = (float)x + 2.5f * fl[0];
    float fy = (float)y + 2.5f * fl[1];
    float x0f = floorf(fx), y0f = floorf(fy);
    int x0 = (int)x0f, y0 = (int)y0f;
    float ax = fx - x0f, ay = fy - y0f;
    bool vx0 = (x0 >= 0) && (x0 <= 127);
    bool vx1 = (x0 + 1 >= 0) && (x0 + 1 <= 127);
    bool vy0 = (y0 >= 0) && (y0 <= 127);
    bool vy1 = (y0 + 1 >= 0) && (y0 + 1 <= 127);
    int xc0 = min(max(x0, 0), 127),     xc1 = min(max(x0 + 1, 0), 127);
    int yc0 = min(max(y0, 0), 127),     yc1 = min(max(y0 + 1, 0), 127);
    float wa = (1.f - ax) * (1.f - ay) * (float)(vx0 && vy0);
    float wb = ax * (1.f - ay)         * (float)(vx1 && vy0);
    float wc = (1.f - ax) * ay         * (float)(vx0 && vy1);
    float wd = ax * ay                 * (float)(vx1 && vy1);
    float ones = wa + wb + wc + wd;
    float m = ones > 0.999f ? 1.f : 0.f;
    wa *= m; wb *= m; wc *= m; wd *= m;
    const float* base = feat2in + (long long)b * FC * HWSZ;
    int o00 = yc0 * WW + xc0, o01 = yc0 * WW + xc1;
    int o10 = yc1 * WW + xc0, o11 = yc1 * WW + xc1;
    float* ob = g_scratch + OF_FEAT2 + (long long)b * FC * HWSZ + y * WW + x;
#pragma unroll 4
    for (int c = 0; c < FC; c++) {
        const float* p = base + (long long)c * HWSZ;
        ob[(long long)c * HWSZ] = wa * __ldg(p + o00) + wb * __ldg(p + o01) +
                                  wc * __ldg(p + o10) + wd * __ldg(p + o11);
    }
}

// ---------------------------------------------------------------------------
// correlation (MD=3 -> 49 displacements, mean over 96 ch) + lrelu — v3.
// (L1-crossbar bound at ~its structural floor; unchanged)
// ---------------------------------------------------------------------------
__global__ __launch_bounds__(256) void corr_k(const float* __restrict__ f1) {
    __shared__ float2 s2[4][8][136];          // 34816 B
    int tid = threadIdx.x;
    int x = tid & 127, ly = tid >> 7;          // ly 0..1
    int y0 = blockIdx.x * 2, b = blockIdx.y;
    int y = y0 + ly;

    float2 acc2[7][3];
    float  acc1[7];
#pragma unroll
    for (int dy = 0; dy < 7; dy++) {
#pragma unroll
        for (int e = 0; e < 3; e++) acc2[dy][e] = make_float2(0.f, 0.f);
        acc1[dy] = 0.f;
    }

    const float* f1b = f1 + (long long)b * FC * HWSZ;
    const float* f2b = g_scratch + OF_FEAT2 + (long long)b * FC * HWSZ;

    int rid = tid >> 3, sub = tid & 7;
    int st_cl = rid >> 3, st_r = rid & 7;
    int st_gy = y0 - 3 + st_r;
    bool rowok = (st_gy >= 0) && (st_gy < HH);
    const float* st_src = f2b + (long long)st_gy * WW;

    for (int c0 = 0; c0 < FC; c0 += 4) {
        {
            const float* src = st_src + (long long)(c0 + st_cl) * HWSZ;
            float2* row = s2[st_cl][st_r];
#pragma unroll
            for (int j = sub; j < 134; j += 8) {
                int gx = j - 3;
                float v = 0.f;
                if (rowok && gx >= 0 && gx < WW) v = __ldg(src + gx);
                row[j].x = v;
                if (j >= 1) row[j - 1].y = v;
            }
        }
        __syncthreads();
        float v1c[4];
#pragma unroll
        for (int cl = 0; cl < 4; cl++)
            v1c[cl] = __ldg(&f1b[(long long)(c0 + cl) * HWSZ + y * WW + x]);
#pragma unroll
        for (int cl = 0; cl < 4; cl++) {
            float  v1 = v1c[cl];
            float2 vv = make_float2(v1, v1);
#pragma unroll
            for (int dy = 0; dy < 7; dy++) {
                const float2* row = s2[cl][ly + dy];
                acc2[dy][0] = ffma2(row[x],     vv, acc2[dy][0]);
                acc2[dy][1] = ffma2(row[x + 2], vv, acc2[dy][1]);
                acc2[dy][2] = ffma2(row[x + 4], vv, acc2[dy][2]);
                acc1[dy] = fmaf(v1, row[x + 6].x, acc1[dy]);
            }
        }
        __syncthreads();
    }

    float* ob = g_scratch + OF_CORR + ((long long)b * 49 * HH + y) * WW + x;
#pragma unroll
    for (int dy = 0; dy < 7; dy++) {
#pragma unroll
        for (int e = 0; e < 3; e++) {
            ob[(long long)(dy * 7 + 2 * e)     * HWSZ] = lrelu(acc2[dy][e].x * (1.f / 96.f));
            ob[(long long)(dy * 7 + 2 * e + 1) * HWSZ] = lrelu(acc2[dy][e].y * (1.f / 96.f));
        }
        ob[(long long)(dy * 7 + 6) * HWSZ] = lrelu(acc1[dy] * (1.f / 96.f));
    }
}

// ---------------------------------------------------------------------------
// 3x3 conv + lrelu, f32x2 packed — v5.
// = v4 (COT=4 tile, input register-prefetch pipeline)
// + double-buffered cp.async weight staging: chunk i+1's weights stream into
//   sW[p^1] via LDGSTS while chunk i computes (zero register cost).
// Per chunk: wait(weights) ; STS input pf ; barrier ;
//            issue cp.async(weights i+1) + LDG(input i+1 -> pf) ;
//            compute ; barrier.
// ---------------------------------------------------------------------------
template <int CIN, int COUT, int CICH>
__global__ __launch_bounds__(256, 2) void conv3x3_k(long long in_off, long long w_off,
                                                    const float* __restrict__ bias,
                                                    long long out_off) {
    constexpr int CO_TILE = 32;
    constexpr int COT = 4;
    constexpr int WCH = CICH * 288;          // float2 per weight buffer
    extern __shared__ float2 dyn[];
    float2* sW  = dyn;                       // [2][CICH][9*32]
    float2* sIn = dyn + 2 * WCH;             // [CICH][4][136]

    const float*  in = g_scratch + in_off;
    const float2* wD = reinterpret_cast<const float2*>(g_scratch + w_off);
    float*       out = g_scratch + out_off;

    int tx = threadIdx.x;                    // 16 -> 8 px each
    int ty = threadIdx.y;                    // 8  -> 4 co each
    int tz = threadIdx.z;                    // 2  -> output row
    int tid = tz * 128 + ty * 16 + tx;
    int y0  = blockIdx.x * 2;
    int y   = y0 + tz;
    int co0 = blockIdx.y * CO_TILE;
    int b   = blockIdx.z;

    const float* inB = in + (long long)b * CIN * HWSZ;

    float2 acc[COT][4];
#pragma unroll
    for (int c = 0; c < COT; c++)
#pragma unroll
        for (int pp = 0; pp < 4; pp++) acc[c][pp] = make_float2(0.f, 0.f);

    // weight async stage: CICH*144 float4 copies, contiguous per (ci,tap)
    auto stage_w_async = [&](int ci0, int p) {
        float4* dst = reinterpret_cast<float4*>(sW + p * WCH);
        for (int i = tid; i < CICH * 144; i += 256) {
            int ci_l = i / 144, r = i - ci_l * 144;
            int tap = r >> 4, c4 = r & 15;
            long long f2i = (long long)((ci0 + ci_l) * 9 + tap) * COUT + co0 + c4 * 2;
            cp_async16(dst + i, reinterpret_cast<const float4*>(wD) + (f2i >> 1));
        }
    };

    // input-staging role: CICH*4 row-units (ci_l*4 + rr), 8 threads each.
    int rid = tid >> 3, sub = tid & 7;
    int st_cil = rid >> 2, st_rr = rid & 3;
    int st_gy  = y0 - 1 + st_rr;
    bool stage_ok = (st_cil < CICH);
    bool rowok = stage_ok && (st_gy >= 0) && (st_gy < HH);
    const float* st_base = inB + (long long)st_cil * HWSZ + (long long)st_gy * WW;

    float pf[17];

    // ---- prologue: async weights chunk 0 + prefetch input chunk 0 ----
    stage_w_async(0, 0);
    CP_COMMIT();
    if (stage_ok) {
#pragma unroll
        for (int k = 0; k < 17; k++) {
            int j = sub + 8 * k;
            if (j < 131) {
                int gx = j - 1;
                float v = 0.f;
                if (rowok && gx >= 0 && gx < WW) v = __ldg(st_base + gx);
                pf[k] = v;
            }
        }
    }

    constexpr int NCHUNK = (CIN + CICH - 1) / CICH;
    for (int cc = 0; cc < NCHUNK; cc++) {
        int ci0 = cc * CICH;
        int p   = cc & 1;
        CP_WAIT0();                          // weights for this chunk resident
        // ---- STS prefetched input (shingled pairs) ----
        if (stage_ok) {
            float2* row = sIn + (st_cil * 4 + st_rr) * 136;
#pragma unroll
            for (int k = 0; k < 17; k++) {
                int j = sub + 8 * k;
                if (j < 131) {
                    float v = pf[k];
                    if (j <= 129) row[(j & 7) * 17 + (j >> 3)].x = v;
                    if (j >= 1) { int u = j - 1; row[(u & 7) * 17 + (u >> 3)].y = v; }
                }
            }
        }
        __syncthreads();
        // ---- issue next chunk's weight cp.async + input prefetch ----
        if (cc + 1 < NCHUNK) {
            stage_w_async(ci0 + CICH, p ^ 1);
            CP_COMMIT();
            if (stage_ok) {
                const float* src = st_base + (long long)(ci0 + CICH) * HWSZ;
#pragma unroll
                for (int k = 0; k < 17; k++) {
                    int j = sub + 8 * k;
                    if (j < 131) {
                        int gx = j - 1;
                        float v = 0.f;
                        if (rowok && gx >= 0 && gx < WW) v = __ldg(src + gx);
                        pf[k] = v;
                    }
                }
            }
        }
        // ---- compute CICH channels from sW[p] ----
        const float2* sWp = sW + p * WCH;
        for (int ci_l = 0; ci_l < CICH; ci_l++) {
            const float2* wRow = sWp + ci_l * 288 + ty * COT;
#pragma unroll
            for (int ky = 0; ky < 3; ky++) {
                const float2* iRow = sIn + (ci_l * 4 + tz + ky) * 136;
                float2 s[9];
#pragma unroll
                for (int q = 0; q < 9; q++) {
                    int u = 8 * tx + q;
                    s[q] = iRow[(u & 7) * 17 + (u >> 3)];
                }
#pragma unroll
                for (int kx = 0; kx < 3; kx++) {
#pragma unroll
                    for (int c = 0; c < COT; c++) {
                        float2 wv = wRow[(ky * 3 + kx) * 32 + c];
#pragma unroll
                        for (int pp = 0; pp < 4; pp++)
                            acc[c][pp] = ffma2(s[kx + 2 * pp], wv, acc[c][pp]);
                    }
                }
            }
        }
        __syncthreads();
    }
    // epilogue: bias + lrelu + store
#pragma unroll
    for (int c = 0; c < COT; c++) {
        int co = co0 + ty * COT + c;
        float bv = __ldg(&bias[co]);
        float* ob = out + (((long long)b * COUT + co) * HH + y) * WW + 8 * tx;
#pragma unroll
        for (int pp = 0; pp < 4; pp++) {
            float2 r = acc[c][pp];
            r.x = lrelu(r.x + bv);
            r.y = lrelu(r.y + bv);
            *reinterpret_cast<float2*>(ob + 2 * pp) = r;
        }
    }
}

// ---------------------------------------------------------------------------
// conv4: 5x5, 32 -> 2 (paired over co), + bias + flow add -> d_out
// ---------------------------------------------------------------------------
__global__ __launch_bounds__(128) void conv4_k(const float* __restrict__ b4,
                                               float* __restrict__ out) {
    __shared__ float s[5][136];
    __shared__ float2 sw[800];
    int x = threadIdx.x;
    int y = blockIdx.x, b = blockIdx.y;
    const float2* w4p = reinterpret_cast<const float2*>(g_scratch + OF_W4P);
    const float* inb  = g_scratch + OF_X3 + (long long)b * 32 * HWSZ;
    for (int i = x; i < 800; i += 128) sw[i] = __ldg(&w4p[i]);
    float2 acc = make_float2(0.f, 0.f);
    for (int ci = 0; ci < 32; ci++) {
        for (int i = x; i < 660; i += 128) {
            int r = i / 132, col = i - r * 132;
            int gy = y - 2 + r, gx = col - 2;
            float v = 0.f;
            if (gy >= 0 && gy < HH && gx >= 0 && gx < WW)
                v = __ldg(&inb[(long long)ci * HWSZ + gy * WW + gx]);
            s[r][col] = v;
        }
        __syncthreads();
#pragma unroll
        for (int ky = 0; ky < 5; ky++)
#pragma unroll
            for (int kx = 0; kx < 5; kx++) {
                float v = s[ky][x + kx];
                float2 vv = make_float2(v, v);
                acc = ffma2(vv, sw[ci * 25 + ky * 5 + kx], acc);
            }
        __syncthreads();
    }
    const float* flow = g_scratch + OF_FLOW;
    long long o0 = ((long long)(b * 2 + 0) * HH + y) * WW + x;
    long long o1 = ((long long)(b * 2 + 1) * HH + y) * WW + x;
    out[o0] = flow[o0] + acc.x + __ldg(&b4[0]);
    out[o1] = flow[o1] + acc.y + __ldg(&b4[1]);
}

// ---------------------------------------------------------------------------
// Launch — order matters for ncu: prep(1), upwarp(2), corr(3), conv1(4)...
// ---------------------------------------------------------------------------
extern "C" void kernel_launch(void* const* d_in, const int* in_sizes, int n_in,
                              void* d_out, int out_size) {
    const float* feat1 = (const float*)d_in[2];
    const float* feat2 = (const float*)d_in[3];
    const float* tflow = (const float*)d_in[4];
    const float* wu    = (const float*)d_in[5];
    const float* w1    = (const float*)d_in[6];
    const float* b1    = (const float*)d_in[7];
    const float* w2    = (const float*)d_in[8];
    const float* b2    = (const float*)d_in[9];
    const float* w3    = (const float*)d_in[10];
    const float* b3    = (const float*)d_in[11];
    const float* w4    = (const float*)d_in[12];
    const float* b4    = (const float*)d_in[13];
    float* out = (float*)d_out;

    // dynamic smem: (2*CICH*288 + CICH*4*136) float2
    const int SM1 = (2 * 7 * 288 + 7 * 4 * 136) * 8;   // 62720
    const int SM2 = (2 * 8 * 288 + 8 * 4 * 136) * 8;   // 71680
    cudaFuncSetAttribute(conv3x3_k<49, 128, 7>, cudaFuncAttributeMaxDynamicSharedMemorySize, SM1);
    cudaFuncSetAttribute(conv3x3_k<128, 64, 8>, cudaFuncAttributeMaxDynamicSharedMemorySize, SM2);
    cudaFuncSetAttribute(conv3x3_k<64, 32, 8>,  cudaFuncAttributeMaxDynamicSharedMemorySize, SM2);

    prep_all_k<<<(128*441 + 64*1152 + 32*576 + 800 + 255) / 256, 256>>>(w1, w2, w3, w4);
    upwarp_k<<<2048, 128>>>(tflow, wu, feat2);
    corr_k<<<dim3(64, 16), 256>>>(feat1);
    conv3x3_k<49, 128, 7><<<dim3(64, 4, 16), dim3(16, 8, 2), SM1>>>(OF_CORR, OF_W1D, b1, OF_X1);
    conv3x3_k<128, 64, 8><<<dim3(64, 2, 16), dim3(16, 8, 2), SM2>>>(OF_X1, OF_W2D, b2, OF_X2);
    conv3x3_k<64, 32, 8><<<dim3(64, 1, 16), dim3(16, 8, 2), SM2>>>(OF_X2, OF_W3D, b3, OF_X3);
    conv4_k<<<dim3(128, 16), 128>>>(b4, out);
}